// round 15
// baseline (speedup 1.0000x reference)
#include <cuda_runtime.h>

// PMLoss with spatially-pruned NN. B=128 ROIs, C=22 classes, P=1024 points.
// grid 512 = 128b x 4 p-chunks, TPB=128.
// Heavy (symmetric) block: counting-sort class points into 4x4x4 cells
// (deterministic), build per-cell rotated centroid+radius, then exact
// NN per p with triangle-inequality pruning (warp-ballot cell skip).
// Light ROI: pc==0 block does all 1024 pointwise; pc>0 write 0.
// Ticket last block sums 512 partials in fixed order -> scalar out.

#define NB 128
#define NC 22
#define NP 1024
#define NCELL 64
#define TPB 128
#define GRID1 (NB * 4)

__device__ float g_part[GRID1];
__device__ unsigned int g_ticket = 0;

__device__ __forceinline__ void quat2mat(float w, float x, float y, float z,
                                         float* R) {
    R[0] = 1.f - 2.f * (y * y + z * z);
    R[1] = 2.f * (x * y - w * z);
    R[2] = 2.f * (x * z + w * y);
    R[3] = 2.f * (x * y + w * z);
    R[4] = 1.f - 2.f * (x * x + z * z);
    R[5] = 2.f * (y * z - w * x);
    R[6] = 2.f * (x * z - w * y);
    R[7] = 2.f * (y * z + w * x);
    R[8] = 1.f - 2.f * (x * x + y * y);
}

__device__ __forceinline__ int cell_of(float x, float y, float z) {
    int cx = (int)floorf((x + 0.125f) * 16.0f);
    int cy = (int)floorf((y + 0.125f) * 16.0f);
    int cz = (int)floorf((z + 0.125f) * 16.0f);
    cx = min(3, max(0, cx));
    cy = min(3, max(0, cy));
    cz = min(3, max(0, cz));
    return cx | (cy << 2) | (cz << 4);
}

__device__ __forceinline__ float block_reduce_128(float d, float* s_red,
                                                  int tid) {
#pragma unroll
    for (int o = 16; o > 0; o >>= 1) d += __shfl_down_sync(0xffffffffu, d, o);
    if ((tid & 31) == 0) s_red[tid >> 5] = d;
    __syncthreads();
    if (tid < 4) {
        d = s_red[tid];
        d += __shfl_down_sync(0xfu, d, 2);
        d += __shfl_down_sync(0xfu, d, 1);
    }
    return d;
}

__global__ __launch_bounds__(TPB) void pm_nn_kernel(
    const float* __restrict__ pred, const float* __restrict__ tgt,
    const float* __restrict__ wt, const float* __restrict__ pts,
    const float* __restrict__ sym, float* __restrict__ out) {
    __shared__ float4 s_buf[NP];      // stage (x,y,z,cell) then rotated tile
    __shared__ float4 s_u[NP];        // sorted unrotated points
    __shared__ float4 s_cell[NCELL];  // rotated centroid xyz, |c|^2
    __shared__ float s_cr[NCELL];     // inflated radius
    __shared__ int s_cnt[NCELL], s_cur[NCELL], s_off[NCELL + 1];
    __shared__ float sR[18];          // Rp 0..8, Rt 9..17
    __shared__ float sM[9];           // M = Rt^T * Rp
    __shared__ int s_cls, s_issym;
    __shared__ float s_red[4];
    __shared__ int s_lastg;

    const int bid = blockIdx.x;
    const int b = bid >> 2;
    const int pc = bid & 3;
    const int tid = threadIdx.x;

    // ---- setup: parallel class find (warp 0), quat->mat + M (lane 0) ----
    if (tid < 32) {
        bool hit = (tid >= 1) && (tid < NC) &&
                   (wt[b * 4 * NC + 4 * tid] > 0.5f);
        unsigned m = __ballot_sync(0xffffffffu, hit);
        if (tid == 0) {
            int cls = m ? (__ffs(m) - 1) : 0;
            s_cls = cls;
            s_issym = (sym[cls] > 0.0f) ? 1 : 0;
            const float* qp = pred + b * 4 * NC + cls * 4;
            float qw = qp[0], qx = qp[1], qy = qp[2], qz = qp[3];
            float inv = rsqrtf(qw * qw + qx * qx + qy * qy + qz * qz);
            quat2mat(qw * inv, qx * inv, qy * inv, qz * inv, sR);
            const float* qt = tgt + b * 4 * NC + cls * 4;  // unit-norm
            quat2mat(qt[0], qt[1], qt[2], qt[3], sR + 9);
            // M = Rt^T * Rp  (maps model point to target-frame query coords)
#pragma unroll
            for (int i = 0; i < 3; i++)
#pragma unroll
                for (int j = 0; j < 3; j++)
                    sM[3 * i + j] = sR[9 + 0 + i] * sR[0 + j] +
                                    sR[9 + 3 + i] * sR[3 + j] +
                                    sR[9 + 6 + i] * sR[6 + j];
        }
    }
    __syncthreads();

    const int issym = s_issym;
    const int cls = s_cls;
    const float* __restrict__ mp = pts + (size_t)cls * NP * 3;
    float dthread = 0.f;
    bool contribute = false;

    if (!issym) {
        if (pc == 0) {
            // all 1024 pointwise: |(Rp - Rt) x|^2, 8 p per thread
            float D0 = sR[0] - sR[9],  D1 = sR[1] - sR[10],
                  D2 = sR[2] - sR[11];
            float D3 = sR[3] - sR[12], D4 = sR[4] - sR[13],
                  D5 = sR[5] - sR[14];
            float D6 = sR[6] - sR[15], D7 = sR[7] - sR[16],
                  D8 = sR[8] - sR[17];
#pragma unroll
            for (int i = 0; i < NP / TPB; i++) {
                int p = tid + i * TPB;
                float x = mp[3 * p + 0], y = mp[3 * p + 1], z = mp[3 * p + 2];
                float dx = D0 * x + D1 * y + D2 * z;
                float dy = D3 * x + D4 * y + D5 * z;
                float dz = D6 * x + D7 * y + D8 * z;
                dthread += dx * dx + dy * dy + dz * dz;
            }
            contribute = true;
        }
        // pc>0 light blocks contribute 0
    } else {
        // ================= heavy: build sorted structure =================
        if (tid < NCELL) s_cnt[tid] = 0;
        __syncthreads();
        // stage: original order (x,y,z,cell) + counts
#pragma unroll
        for (int i = tid; i < NP; i += TPB) {
            float x = mp[3 * i + 0], y = mp[3 * i + 1], z = mp[3 * i + 2];
            int c = cell_of(x, y, z);
            s_buf[i] = make_float4(x, y, z, (float)c);
            atomicAdd(&s_cnt[c], 1);
        }
        __syncthreads();
        if (tid == 0) {           // exclusive scan
            int acc = 0;
#pragma unroll
            for (int c = 0; c < NCELL; c++) {
                s_off[c] = acc;
                acc += s_cnt[c];
            }
            s_off[NCELL] = acc;
        }
        __syncthreads();
        if (tid < NCELL) s_cur[tid] = s_off[tid];
        __syncthreads();
        // deterministic scatter by warp 0 (match_any ranking)
        if (tid < 32) {
            for (int it = 0; it < NP / 32; it++) {
                int i = it * 32 + tid;
                float4 st = s_buf[i];
                int c = (int)st.w;
                unsigned mk = __match_any_sync(0xffffffffu, c);
                int leader = __ffs(mk) - 1;
                int base = 0;
                if (tid == leader) base = atomicAdd(&s_cur[c], __popc(mk));
                base = __shfl_sync(0xffffffffu, base, leader);
                int pos = base + __popc(mk & ((1u << tid) - 1u));
                s_u[pos] = make_float4(st.x, st.y, st.z, 0.f);
            }
        }
        __syncthreads();
        // rotated tile (overwrites stage) + cell bounds
        {
            float T0 = sR[9],  T1 = sR[10], T2 = sR[11];
            float T3 = sR[12], T4 = sR[13], T5 = sR[14];
            float T6 = sR[15], T7 = sR[16], T8 = sR[17];
#pragma unroll
            for (int i = tid; i < NP; i += TPB) {
                float4 uu = s_u[i];
                float tx = T0 * uu.x + T1 * uu.y + T2 * uu.z;
                float ty = T3 * uu.x + T4 * uu.y + T5 * uu.z;
                float tz = T6 * uu.x + T7 * uu.y + T8 * uu.z;
                s_buf[i] =
                    make_float4(tx, ty, tz, tx * tx + ty * ty + tz * tz);
            }
            if (tid < NCELL) {
                int beg = s_off[tid], end = s_off[tid + 1];
                float mx = 0.f, my = 0.f, mz = 0.f;
                for (int k = beg; k < end; k++) {
                    float4 uu = s_u[k];
                    mx += uu.x; my += uu.y; mz += uu.z;
                }
                int n = end - beg;
                float invn = (n > 0) ? (1.0f / (float)n) : 0.f;
                mx *= invn; my *= invn; mz *= invn;
                float r2 = 0.f;
                for (int k = beg; k < end; k++) {
                    float4 uu = s_u[k];
                    float dx = uu.x - mx, dy = uu.y - my, dz = uu.z - mz;
                    r2 = fmaxf(r2, dx * dx + dy * dy + dz * dz);
                }
                float r = sqrtf(r2) * 1.0002f + 1e-6f;
                float cx = T0 * mx + T1 * my + T2 * mz;
                float cy = T3 * mx + T4 * my + T5 * mz;
                float cz = T6 * mx + T7 * my + T8 * mz;
                s_cell[tid] =
                    make_float4(cx, cy, cz, cx * cx + cy * cy + cz * cz);
                s_cr[tid] = r;
            }
        }
        __syncthreads();

        // ================= NN for 2 sorted p's per thread =================
        const int p0 = pc * 256 + tid;
        const int p1 = p0 + TPB;
        float4 u0 = s_u[p0], u1 = s_u[p1];
        float P0 = sR[0], P1 = sR[1], P2 = sR[2];
        float P3 = sR[3], P4 = sR[4], P5 = sR[5];
        float P6 = sR[6], P7 = sR[7], P8 = sR[8];
        float px0 = P0 * u0.x + P1 * u0.y + P2 * u0.z;
        float py0 = P3 * u0.x + P4 * u0.y + P5 * u0.z;
        float pz0 = P6 * u0.x + P7 * u0.y + P8 * u0.z;
        float px1 = P0 * u1.x + P1 * u1.y + P2 * u1.z;
        float py1 = P3 * u1.x + P4 * u1.y + P5 * u1.z;
        float pz1 = P6 * u1.x + P7 * u1.y + P8 * u1.z;
        float ppn0 = px0 * px0 + py0 * py0 + pz0 * pz0;
        float ppn1 = px1 * px1 + py1 * py1 + pz1 * pz1;
        float a0x = -2.f * px0, a0y = -2.f * py0, a0z = -2.f * pz0;
        float a1x = -2.f * px1, a1y = -2.f * py1, a1z = -2.f * pz1;
        // seed cells from query in model space: u = M * x
        float q0x = sM[0] * u0.x + sM[1] * u0.y + sM[2] * u0.z;
        float q0y = sM[3] * u0.x + sM[4] * u0.y + sM[5] * u0.z;
        float q0z = sM[6] * u0.x + sM[7] * u0.y + sM[8] * u0.z;
        float q1x = sM[0] * u1.x + sM[1] * u1.y + sM[2] * u1.z;
        float q1y = sM[3] * u1.x + sM[4] * u1.y + sM[5] * u1.z;
        float q1z = sM[6] * u1.x + sM[7] * u1.y + sM[8] * u1.z;
        int c00 = cell_of(q0x, q0y, q0z);
        int c01 = cell_of(q1x, q1y, q1z);

        const float INF = 3.402823466e38f;
        float m0 = INF, m1 = INF;

        // evaluate the union of seed cells across the warp
#pragma unroll
        for (int si = 0; si < 2; si++) {
            int myc = si ? c01 : c00;
            unsigned pend = 0xffffffffu;
            while (pend) {
                int leader = __ffs(pend) - 1;
                int c = __shfl_sync(0xffffffffu, myc, leader);
                pend &= ~__ballot_sync(0xffffffffu, myc == c);
                int beg = s_off[c], end = s_off[c + 1];
                for (int k = beg; k < end; k++) {
                    float4 t = s_buf[k];
                    float v0 = fmaf(a0x, t.x,
                               fmaf(a0y, t.y, fmaf(a0z, t.z, t.w)));
                    float v1 = fmaf(a1x, t.x,
                               fmaf(a1y, t.y, fmaf(a1z, t.z, t.w)));
                    m0 = fminf(m0, v0);
                    m1 = fminf(m1, v1);
                }
            }
        }
        float s0 = sqrtf(fmaxf(m0 + ppn0, 0.f));
        float s1 = sqrtf(fmaxf(m1 + ppn1, 0.f));

        // sweep all cells with conservative triangle-inequality pruning
        for (int c = 0; c < NCELL; c++) {
            float4 cc = s_cell[c];
            float r = s_cr[c];
            float dc0 = fmaf(a0x, cc.x,
                        fmaf(a0y, cc.y, fmaf(a0z, cc.z, ppn0 + cc.w)));
            float dc1 = fmaf(a1x, cc.x,
                        fmaf(a1y, cc.y, fmaf(a1z, cc.z, ppn1 + cc.w)));
            float t0 = s0 + r, t1 = s1 + r;
            bool need = (c != c00 || c != c01) &&
                        ((c != c00 && dc0 < t0 * t0 * 1.0001f) ||
                         (c != c01 && dc1 < t1 * t1 * 1.0001f));
            if (__ballot_sync(0xffffffffu, need)) {
                int beg = s_off[c], end = s_off[c + 1];
                for (int k = beg; k < end; k++) {
                    float4 t = s_buf[k];
                    float v0 = fmaf(a0x, t.x,
                               fmaf(a0y, t.y, fmaf(a0z, t.z, t.w)));
                    float v1 = fmaf(a1x, t.x,
                               fmaf(a1y, t.y, fmaf(a1z, t.z, t.w)));
                    m0 = fminf(m0, v0);
                    m1 = fminf(m1, v1);
                }
                s0 = sqrtf(fmaxf(m0 + ppn0, 0.f));
                s1 = sqrtf(fmaxf(m1 + ppn1, 0.f));
            }
        }
        dthread = (m0 + ppn0) + (m1 + ppn1);
        contribute = true;
    }

    // ---- block partial (uniform per block) ----
    float tot = 0.f;
    if (contribute) {
        tot = block_reduce_128(dthread, s_red, tid);
    }
    __syncthreads();
    if (tid == 0) {
        g_part[bid] = contribute ? tot : 0.f;
        __threadfence();
        unsigned t = atomicAdd(&g_ticket, 1u);
        s_lastg = (t == GRID1 - 1) ? 1 : 0;
        if (t == GRID1 - 1) __threadfence();
    }
    __syncthreads();
    if (!s_lastg) return;

    // ---- final: fixed-order 512-way sum ----
    float v = 0.f;
#pragma unroll
    for (int i = 0; i < GRID1 / TPB; i++)
        v += __ldcg(&g_part[tid + i * TPB]);
    float total = block_reduce_128(v, s_red, tid);
    if (tid == 0) {
        out[0] = total * (1.0f / (2.0f * NB * NP));
        g_ticket = 0;   // reset for next replay
    }
}

extern "C" void kernel_launch(void* const* d_in, const int* in_sizes, int n_in,
                              void* d_out, int out_size) {
    const float* pred = (const float*)d_in[0];
    const float* tgt  = (const float*)d_in[1];
    const float* wt   = (const float*)d_in[2];
    const float* pts  = (const float*)d_in[3];
    const float* sym  = (const float*)d_in[4];
    float* out = (float*)d_out;

    pm_nn_kernel<<<GRID1, TPB>>>(pred, tgt, wt, pts, sym, out);
}

// round 16
// speedup vs baseline: 2.5540x; 2.5540x over previous
#include <cuda_runtime.h>

// PMLoss, 2-D tiled, single fused kernel, scalar inner loop, 4 p/thread.
// B=128 ROIs, C=22 classes, P=1024 points.
// grid 2048 = 128b x 2 p-chunks x 8 q-chunks, TPB=128.
// Each thread owns 4 p's -> each q-tile LDS.128 feeds 4 points (4.6
// issue slots per (p,q) pair vs 5.25 at 2 p/thread).
// Heavy block: partial min over its 128-q float4 smem tile -> g_dmin[b][qc][p].
// Light block (qc==0 only): pointwise d -> g_dmin[b][0][p].
// tid0-only fences (CUB last-block pattern); per-b ticket combine; global
// ticket final sum. All arithmetic orders fixed -> deterministic.

#define NB 128
#define NC 22
#define NP 1024
#define PC 2
#define QC 8
#define PPB (NP / PC)     // 512 p per block (4 per thread)
#define QPB (NP / QC)     // 128 q per block
#define TPB 128
#define GRID1 (NB * PC * QC)   // 2048

__device__ float g_dmin[NB][QC][NP];   // 4 MB scratch
__device__ float g_partials[NB];
__device__ int   g_ticket_b[NB];
__device__ unsigned int g_ticket = 0;

__device__ __forceinline__ void quat2mat(float w, float x, float y, float z,
                                         float* R) {
    R[0] = 1.f - 2.f * (y * y + z * z);
    R[1] = 2.f * (x * y - w * z);
    R[2] = 2.f * (x * z + w * y);
    R[3] = 2.f * (x * y + w * z);
    R[4] = 1.f - 2.f * (x * x + z * z);
    R[5] = 2.f * (y * z - w * x);
    R[6] = 2.f * (x * z - w * y);
    R[7] = 2.f * (y * z + w * x);
    R[8] = 1.f - 2.f * (x * x + y * y);
}

__device__ __forceinline__ float block_reduce_128(float d, float* s_red,
                                                  int tid) {
#pragma unroll
    for (int o = 16; o > 0; o >>= 1) d += __shfl_down_sync(0xffffffffu, d, o);
    if ((tid & 31) == 0) s_red[tid >> 5] = d;
    __syncthreads();
    if (tid < 4) {
        d = s_red[tid];
        d += __shfl_down_sync(0xfu, d, 2);
        d += __shfl_down_sync(0xfu, d, 1);
    }
    return d;
}

__global__ __launch_bounds__(TPB) void pm_fused_kernel(
    const float* __restrict__ pred, const float* __restrict__ tgt,
    const float* __restrict__ wt, const float* __restrict__ pts,
    const float* __restrict__ sym, float* __restrict__ out) {
    __shared__ float4 s_pt[QPB];      // target-rotated q tile: (x,y,z,|t|^2)
    __shared__ float sR[18];          // Rp 0..8, Rt 9..17
    __shared__ int s_cls, s_issym;
    __shared__ float s_red[4];
    __shared__ int s_lastb, s_lastg;

    const int bid = blockIdx.x;
    const int b = bid >> 4;
    const int pc = (bid >> 3) & 1;
    const int qc = bid & 7;
    const int tid = threadIdx.x;

    // ---- setup: parallel class find (warp 0), quat->mat (lane 0) ----
    if (tid < 32) {
        bool hit = (tid >= 1) && (tid < NC) &&
                   (wt[b * 4 * NC + 4 * tid] > 0.5f);
        unsigned m = __ballot_sync(0xffffffffu, hit);
        if (tid == 0) {
            int cls = m ? (__ffs(m) - 1) : 0;
            s_cls = cls;
            s_issym = (sym[cls] > 0.0f) ? 1 : 0;
            const float* qp = pred + b * 4 * NC + cls * 4;
            float qw = qp[0], qx = qp[1], qy = qp[2], qz = qp[3];
            float inv = rsqrtf(qw * qw + qx * qx + qy * qy + qz * qz);
            quat2mat(qw * inv, qx * inv, qy * inv, qz * inv, sR);
            const float* qt = tgt + b * 4 * NC + cls * 4;  // unit-norm
            quat2mat(qt[0], qt[1], qt[2], qt[3], sR + 9);
        }
    }
    __syncthreads();

    const int issym = s_issym;
    const int cls = s_cls;
    const float* __restrict__ mp = pts + (size_t)cls * NP * 3;

    if (!issym) {
        if (qc == 0) {
            // Pointwise |(Rp-Rt) x|^2 for this block's 512 p's (4/thread).
            float D0 = sR[0] - sR[9],  D1 = sR[1] - sR[10],
                  D2 = sR[2] - sR[11];
            float D3 = sR[3] - sR[12], D4 = sR[4] - sR[13],
                  D5 = sR[5] - sR[14];
            float D6 = sR[6] - sR[15], D7 = sR[7] - sR[16],
                  D8 = sR[8] - sR[17];
#pragma unroll
            for (int k = 0; k < 4; k++) {
                int p = pc * PPB + k * TPB + tid;
                float x = mp[3 * p + 0], y = mp[3 * p + 1], z = mp[3 * p + 2];
                float dx = D0 * x + D1 * y + D2 * z;
                float dy = D3 * x + D4 * y + D5 * z;
                float dz = D6 * x + D7 * y + D8 * z;
                g_dmin[b][0][p] = dx * dx + dy * dy + dz * dz;
            }
        }
    } else {
        // ---- heavy: fill this block's 128-q target tile ----
        if (tid < QPB) {
            float T0 = sR[9],  T1 = sR[10], T2 = sR[11];
            float T3 = sR[12], T4 = sR[13], T5 = sR[14];
            float T6 = sR[15], T7 = sR[16], T8 = sR[17];
            int q = qc * QPB + tid;
            float x = mp[3 * q + 0], y = mp[3 * q + 1], z = mp[3 * q + 2];
            float tx = T0 * x + T1 * y + T2 * z;
            float ty = T3 * x + T4 * y + T5 * z;
            float tz = T6 * x + T7 * y + T8 * z;
            s_pt[tid] = make_float4(tx, ty, tz, tx * tx + ty * ty + tz * tz);
        }
        // predicted-rotated p's (4 per thread)
        float ax[4], ay[4], az[4], pn[4];
        {
            float P0 = sR[0], P1 = sR[1], P2 = sR[2];
            float P3 = sR[3], P4 = sR[4], P5 = sR[5];
            float P6 = sR[6], P7 = sR[7], P8 = sR[8];
#pragma unroll
            for (int k = 0; k < 4; k++) {
                int p = pc * PPB + k * TPB + tid;
                float x = mp[3 * p + 0], y = mp[3 * p + 1], z = mp[3 * p + 2];
                float px = P0 * x + P1 * y + P2 * z;
                float py = P3 * x + P4 * y + P5 * z;
                float pz = P6 * x + P7 * y + P8 * z;
                ax[k] = -2.f * px;
                ay[k] = -2.f * py;
                az[k] = -2.f * pz;
                pn[k] = px * px + py * py + pz * pz;
            }
        }
        __syncthreads();

        const float INF = 3.402823466e38f;
        float ma[4] = {INF, INF, INF, INF};   // even-q accumulators
        float mb[4] = {INF, INF, INF, INF};   // odd-q accumulators

#pragma unroll 2
        for (int j = 0; j < QPB / 2; j++) {
            float4 t0 = s_pt[2 * j];
            float4 t1 = s_pt[2 * j + 1];
#pragma unroll
            for (int k = 0; k < 4; k++) {
                float v;
                v = fmaf(ax[k], t0.x, t0.w);
                v = fmaf(ay[k], t0.y, v);
                v = fmaf(az[k], t0.z, v);
                ma[k] = fminf(ma[k], v);
                v = fmaf(ax[k], t1.x, t1.w);
                v = fmaf(ay[k], t1.y, v);
                v = fmaf(az[k], t1.z, v);
                mb[k] = fminf(mb[k], v);
            }
        }
#pragma unroll
        for (int k = 0; k < 4; k++) {
            int p = pc * PPB + k * TPB + tid;
            g_dmin[b][qc][p] = fminf(ma[k], mb[k]) + pn[k];
        }
    }

    // ---- release + per-b ticket (tid0-only fence; bar orders all stores) ----
    __syncthreads();
    if (tid == 0) {
        __threadfence();      // release this block's g_dmin stores
        int t = atomicAdd(&g_ticket_b[b], 1);
        s_lastb = (t == PC * QC - 1) ? 1 : 0;
        if (t == PC * QC - 1) __threadfence();   // acquire peers' stores
    }
    __syncthreads();
    if (!s_lastb) return;

    // ---- combine for ROI b (last of its 16 blocks; data is L2-hot) ----
    float acc = 0.f;
#pragma unroll
    for (int i = 0; i < NP / TPB; i++) {
        int p = tid + i * TPB;
        float dv = __ldcg(&g_dmin[b][0][p]);
        if (issym) {
#pragma unroll
            for (int k = 1; k < QC; k++)
                dv = fminf(dv, __ldcg(&g_dmin[b][k][p]));
        }
        acc += dv;
    }
    float tot = block_reduce_128(acc, s_red, tid);
    if (tid == 0) {
        g_partials[b] = tot;
        __threadfence();      // release partial
        unsigned t = atomicAdd(&g_ticket, 1u);
        s_lastg = (t == NB - 1) ? 1 : 0;
        if (t == NB - 1) __threadfence();        // acquire all partials
    }
    __syncthreads();
    if (!s_lastg) return;

    // ---- final: fixed-order 128-way sum, write scalar, reset tickets ----
    float v = __ldcg(&g_partials[tid]);
    float total = block_reduce_128(v, s_red, tid);
    g_ticket_b[tid] = 0;       // reset per-b tickets for next replay
    if (tid == 0) {
        out[0] = total * (1.0f / (2.0f * NB * NP));
        g_ticket = 0;
    }
}

extern "C" void kernel_launch(void* const* d_in, const int* in_sizes, int n_in,
                              void* d_out, int out_size) {
    const float* pred = (const float*)d_in[0];
    const float* tgt  = (const float*)d_in[1];
    const float* wt   = (const float*)d_in[2];
    const float* pts  = (const float*)d_in[3];
    const float* sym  = (const float*)d_in[4];
    float* out = (float*)d_out;

    pm_fused_kernel<<<GRID1, TPB>>>(pred, tgt, wt, pts, sym, out);
}

// round 17
// speedup vs baseline: 3.5049x; 1.3723x over previous
#include <cuda_runtime.h>
#include <cstdint>

// PMLoss via TF32 tensor-core distance matrix. B=128, C=22, P=1024.
// grid 1024 = 128b x 8 p-chunks, TPB=128 (4 warps).
// Heavy (symmetric) block: chunk of 128 p's vs ALL 1024 q's.
//   d2(p,q) = |pt_q|^2 - 2 pp.pt_q + |pp_p|^2.
//   mma.sync.m16n8k8.tf32: A = tf32(-2*pp) [16x8, K=3 padded], B = tf32(pt),
//   C-init = |pt_q|^2 (exact fp32). Result min-reduced per row; |pp|^2 (exact
//   fp32) added after the min. Each warp: 32 rows x 1024 cols.
// Light block: pointwise |(Rp-Rt)x|^2 for its 128 p's.
// Block sums -> g_part[1024]; global ticket last block -> scalar out.

#define NB 128
#define NC 22
#define NP 1024
#define PC 8
#define PPB (NP / PC)     // 128 p per block
#define TPB 128
#define GRID1 (NB * PC)   // 1024

__device__ float g_part[GRID1];
__device__ unsigned int g_ticket = 0;

__device__ __forceinline__ void quat2mat(float w, float x, float y, float z,
                                         float* R) {
    R[0] = 1.f - 2.f * (y * y + z * z);
    R[1] = 2.f * (x * y - w * z);
    R[2] = 2.f * (x * z + w * y);
    R[3] = 2.f * (x * y + w * z);
    R[4] = 1.f - 2.f * (x * x + z * z);
    R[5] = 2.f * (y * z - w * x);
    R[6] = 2.f * (x * z - w * y);
    R[7] = 2.f * (y * z + w * x);
    R[8] = 1.f - 2.f * (x * x + y * y);
}

__device__ __forceinline__ uint32_t to_tf32(float f) {
    uint32_t r;
    asm("cvt.rna.tf32.f32 %0, %1;" : "=r"(r) : "f"(f));
    return r;
}

__device__ __forceinline__ void mma_tf32(
    float& d0, float& d1, float& d2, float& d3,
    uint32_t a0, uint32_t a1, uint32_t a2, uint32_t a3,
    uint32_t b0, uint32_t b1,
    float c0, float c1, float c2, float c3) {
    asm volatile(
        "mma.sync.aligned.m16n8k8.row.col.f32.tf32.tf32.f32 "
        "{%0,%1,%2,%3}, {%4,%5,%6,%7}, {%8,%9}, {%10,%11,%12,%13};\n"
        : "=f"(d0), "=f"(d1), "=f"(d2), "=f"(d3)
        : "r"(a0), "r"(a1), "r"(a2), "r"(a3), "r"(b0), "r"(b1),
          "f"(c0), "f"(c1), "f"(c2), "f"(c3));
}

__device__ __forceinline__ float block_reduce_128(float d, float* s_red,
                                                  int tid) {
#pragma unroll
    for (int o = 16; o > 0; o >>= 1) d += __shfl_down_sync(0xffffffffu, d, o);
    if ((tid & 31) == 0) s_red[tid >> 5] = d;
    __syncthreads();
    if (tid < 4) {
        d = s_red[tid];
        d += __shfl_down_sync(0xfu, d, 2);
        d += __shfl_down_sync(0xfu, d, 1);
    }
    return d;
}

__global__ __launch_bounds__(TPB) void pm_tc_kernel(
    const float* __restrict__ pred, const float* __restrict__ tgt,
    const float* __restrict__ wt, const float* __restrict__ pts,
    const float* __restrict__ sym, float* __restrict__ out) {
    __shared__ uint32_t sB4[NP * 4];   // tf32 {tx,ty,tz,0} per q  (16 KB)
    __shared__ float sW[NP];           // |pt_q|^2 exact fp32      (4 KB)
    __shared__ uint32_t sA4[PPB * 4];  // tf32 {-2px,-2py,-2pz,0}  (2 KB)
    __shared__ float sPN[PPB];         // |pp_p|^2 exact fp32
    __shared__ float sR[18];           // Rp 0..8, Rt 9..17
    __shared__ int s_cls, s_issym;
    __shared__ float s_red[4];
    __shared__ int s_lastg;

    const int bid = blockIdx.x;
    const int b = bid >> 3;
    const int pc = bid & 7;
    const int tid = threadIdx.x;

    // ---- setup: parallel class find (warp 0), quat->mat (lane 0) ----
    if (tid < 32) {
        bool hit = (tid >= 1) && (tid < NC) &&
                   (wt[b * 4 * NC + 4 * tid] > 0.5f);
        unsigned m = __ballot_sync(0xffffffffu, hit);
        if (tid == 0) {
            int cls = m ? (__ffs(m) - 1) : 0;
            s_cls = cls;
            s_issym = (sym[cls] > 0.0f) ? 1 : 0;
            const float* qp = pred + b * 4 * NC + cls * 4;
            float qw = qp[0], qx = qp[1], qy = qp[2], qz = qp[3];
            float inv = rsqrtf(qw * qw + qx * qx + qy * qy + qz * qz);
            quat2mat(qw * inv, qx * inv, qy * inv, qz * inv, sR);
            const float* qt = tgt + b * 4 * NC + cls * 4;  // unit-norm
            quat2mat(qt[0], qt[1], qt[2], qt[3], sR + 9);
        }
    }
    __syncthreads();

    const int issym = s_issym;
    const int cls = s_cls;
    const float* __restrict__ mp = pts + (size_t)cls * NP * 3;
    float dthread = 0.f;

    if (!issym) {
        // ---- light: pointwise |(Rp-Rt) x|^2 for this chunk's 128 p's ----
        float D0 = sR[0] - sR[9],  D1 = sR[1] - sR[10], D2 = sR[2] - sR[11];
        float D3 = sR[3] - sR[12], D4 = sR[4] - sR[13], D5 = sR[5] - sR[14];
        float D6 = sR[6] - sR[15], D7 = sR[7] - sR[16], D8 = sR[8] - sR[17];
        int p = pc * PPB + tid;
        float x = mp[3 * p + 0], y = mp[3 * p + 1], z = mp[3 * p + 2];
        float dx = D0 * x + D1 * y + D2 * z;
        float dy = D3 * x + D4 * y + D5 * z;
        float dz = D6 * x + D7 * y + D8 * z;
        dthread = dx * dx + dy * dy + dz * dz;
    } else {
        // ---- heavy: build B (all q) and A (this chunk's 128 p's) ----
        {
            float T0 = sR[9],  T1 = sR[10], T2 = sR[11];
            float T3 = sR[12], T4 = sR[13], T5 = sR[14];
            float T6 = sR[15], T7 = sR[16], T8 = sR[17];
#pragma unroll
            for (int q = tid; q < NP; q += TPB) {
                float x = mp[3 * q + 0], y = mp[3 * q + 1], z = mp[3 * q + 2];
                float tx = T0 * x + T1 * y + T2 * z;
                float ty = T3 * x + T4 * y + T5 * z;
                float tz = T6 * x + T7 * y + T8 * z;
                sB4[q * 4 + 0] = to_tf32(tx);
                sB4[q * 4 + 1] = to_tf32(ty);
                sB4[q * 4 + 2] = to_tf32(tz);
                sB4[q * 4 + 3] = 0u;
                sW[q] = tx * tx + ty * ty + tz * tz;  // exact fp32
            }
            float P0 = sR[0], P1 = sR[1], P2 = sR[2];
            float P3 = sR[3], P4 = sR[4], P5 = sR[5];
            float P6 = sR[6], P7 = sR[7], P8 = sR[8];
            int p = pc * PPB + tid;
            float x = mp[3 * p + 0], y = mp[3 * p + 1], z = mp[3 * p + 2];
            float px = P0 * x + P1 * y + P2 * z;
            float py = P3 * x + P4 * y + P5 * z;
            float pz = P6 * x + P7 * y + P8 * z;
            sA4[tid * 4 + 0] = to_tf32(-2.f * px);
            sA4[tid * 4 + 1] = to_tf32(-2.f * py);
            sA4[tid * 4 + 2] = to_tf32(-2.f * pz);
            sA4[tid * 4 + 3] = 0u;
            sPN[tid] = px * px + py * py + pz * pz;   // exact fp32
        }
        __syncthreads();

        const int lane = tid & 31;
        const int wid = tid >> 5;
        const int g = lane >> 2;     // 0..7
        const int tig = lane & 3;    // 0..3
        // warp handles local rows [wid*32, wid*32+32): rg0 = rows base+g,
        // base+g+8 ; rg1 = rows base+16+g, base+16+g+8.
        const int r00 = wid * 32 + g;
        const int r01 = r00 + 8;
        const int r10 = wid * 32 + 16 + g;
        const int r11 = r10 + 8;

        const uint32_t a00 = sA4[r00 * 4 + tig];
        const uint32_t a01 = sA4[r01 * 4 + tig];
        const uint32_t a10 = sA4[r10 * 4 + tig];
        const uint32_t a11 = sA4[r11 * 4 + tig];
        const uint32_t zz = 0u;
        const float pn00 = sPN[r00], pn01 = sPN[r01];
        const float pn10 = sPN[r10], pn11 = sPN[r11];

        const float INF = 3.402823466e38f;
        float rm00 = INF, rm01 = INF, rm10 = INF, rm11 = INF;

#pragma unroll 4
        for (int cg = 0; cg < NP / 8; cg++) {
            uint32_t b0 = sB4[(cg * 8 + g) * 4 + tig];
            float2 c01 = *(const float2*)&sW[cg * 8 + tig * 2];
            float d0, d1, d2, d3, e0, e1, e2, e3;
            mma_tf32(d0, d1, d2, d3, a00, a01, zz, zz, b0, zz,
                     c01.x, c01.y, c01.x, c01.y);
            mma_tf32(e0, e1, e2, e3, a10, a11, zz, zz, b0, zz,
                     c01.x, c01.y, c01.x, c01.y);
            rm00 = fminf(rm00, fminf(d0, d1));
            rm01 = fminf(rm01, fminf(d2, d3));
            rm10 = fminf(rm10, fminf(e0, e1));
            rm11 = fminf(rm11, fminf(e2, e3));
        }
        // quad-min across tig (lanes 4g..4g+3 share rows)
#pragma unroll
        for (int o = 1; o <= 2; o <<= 1) {
            rm00 = fminf(rm00, __shfl_xor_sync(0xffffffffu, rm00, o));
            rm01 = fminf(rm01, __shfl_xor_sync(0xffffffffu, rm01, o));
            rm10 = fminf(rm10, __shfl_xor_sync(0xffffffffu, rm10, o));
            rm11 = fminf(rm11, __shfl_xor_sync(0xffffffffu, rm11, o));
        }
        dthread = (tig == 0)
                      ? ((rm00 + pn00) + (rm01 + pn01) +
                         (rm10 + pn10) + (rm11 + pn11))
                      : 0.f;
    }

    // ---- block partial + global ticket ----
    float tot = block_reduce_128(dthread, s_red, tid);
    __syncthreads();
    if (tid == 0) {
        g_part[bid] = tot;
        __threadfence();      // release
        unsigned t = atomicAdd(&g_ticket, 1u);
        s_lastg = (t == GRID1 - 1) ? 1 : 0;
        if (t == GRID1 - 1) __threadfence();   // acquire
    }
    __syncthreads();
    if (!s_lastg) return;

    // ---- final: fixed-order 1024-way sum ----
    float v = 0.f;
#pragma unroll
    for (int i = 0; i < GRID1 / TPB; i++)
        v += __ldcg(&g_part[tid + i * TPB]);
    float total = block_reduce_128(v, s_red, tid);
    if (tid == 0) {
        out[0] = total * (1.0f / (2.0f * NB * NP));
        g_ticket = 0;   // reset for next replay
    }
}

extern "C" void kernel_launch(void* const* d_in, const int* in_sizes, int n_in,
                              void* d_out, int out_size) {
    const float* pred = (const float*)d_in[0];
    const float* tgt  = (const float*)d_in[1];
    const float* wt   = (const float*)d_in[2];
    const float* pts  = (const float*)d_in[3];
    const float* sym  = (const float*)d_in[4];
    float* out = (float*)d_out;

    pm_tc_kernel<<<GRID1, TPB>>>(pred, tgt, wt, pts, sym, out);
}